// round 2
// baseline (speedup 1.0000x reference)
#include <cuda_runtime.h>
#include <math.h>

#define FULL 0xffffffffu
#define B_     2
#define C_     512
#define N_     4096
#define HEADS_ 8
#define DH_    64
#define KMAX_  32

// ---------------- scratch (device globals; no allocation allowed) ----------------
__device__ float g_Q[B_ * HEADS_ * DH_ * N_];   // [b][h][d][n]
__device__ float g_K[B_ * HEADS_ * DH_ * N_];   // [b][h][d][n]
__device__ float g_V[B_ * HEADS_ * N_ * DH_];   // [b][h][n][d]
__device__ float g_A[B_ * C_ * N_];             // attention out, [b][c][n], c = h*64+d
__device__ int   g_kdyn[B_ * N_];

// ---------------- helpers ----------------
__device__ __forceinline__ unsigned ordf(float v) {
    unsigned u = __float_as_uint(v);
    return (u & 0x80000000u) ? ~u : (u | 0x80000000u);
}
__device__ __forceinline__ float iordf(unsigned o) {
    unsigned u = (o & 0x80000000u) ? (o & 0x7fffffffu) : ~o;
    return __uint_as_float(u);
}

// ================= kernel 1: QKV GEMM =================
// out[o][n] = sum_c w[o][c] * x[b][c][n];  o-tile 64, n-tile 128
// Q,K stored [b][h][d][n]; V stored [b][h][n][d] (smem transpose)
__global__ __launch_bounds__(256) void qkv_gemm_kernel(const float* __restrict__ x,
                                                       const float* __restrict__ w) {
    __shared__ float Ws[16][68];
    __shared__ float Xs[16][132];
    __shared__ float St[64][132];
    int n0 = blockIdx.x * 128;
    int o0 = blockIdx.y * 64;
    int b  = blockIdx.z;
    int tid = threadIdx.x;
    int ty = tid >> 4, tx = tid & 15;
    const float* xb = x + b * C_ * N_;

    float acc[4][8];
#pragma unroll
    for (int a = 0; a < 4; a++)
#pragma unroll
        for (int c = 0; c < 8; c++) acc[a][c] = 0.f;

    for (int c0 = 0; c0 < C_; c0 += 16) {
        {   // W tile transpose-load: Ws[cc][oo]
            int oo = tid >> 2;
            int cc4 = (tid & 3) << 2;
            float4 wv = *(const float4*)(w + (o0 + oo) * C_ + c0 + cc4);
            Ws[cc4 + 0][oo] = wv.x; Ws[cc4 + 1][oo] = wv.y;
            Ws[cc4 + 2][oo] = wv.z; Ws[cc4 + 3][oo] = wv.w;
        }
#pragma unroll
        for (int r = 0; r < 2; r++) {   // X tile: Xs[cc][nn]
            int f = tid + r * 256;
            int cc = f >> 5, n4 = (f & 31) << 2;
            *(float4*)&Xs[cc][n4] = *(const float4*)(xb + (c0 + cc) * N_ + n0 + n4);
        }
        __syncthreads();
#pragma unroll
        for (int cc = 0; cc < 16; cc++) {
            float4 wv = *(float4*)&Ws[cc][ty * 4];
            float4 x0 = *(float4*)&Xs[cc][tx * 8];
            float4 x1 = *(float4*)&Xs[cc][tx * 8 + 4];
            float wr[4] = {wv.x, wv.y, wv.z, wv.w};
            float xr[8] = {x0.x, x0.y, x0.z, x0.w, x1.x, x1.y, x1.z, x1.w};
#pragma unroll
            for (int a = 0; a < 4; a++)
#pragma unroll
                for (int c = 0; c < 8; c++) acc[a][c] += wr[a] * xr[c];
        }
        __syncthreads();
    }

    int sel = o0 >> 9;            // 0:Q 1:K 2:V
    int h   = (o0 & 511) >> 6;    // head (o-tiles are 64-aligned => full head per tile)
    if (sel < 2) {
        float* dst = (sel == 0 ? g_Q : g_K) + (b * HEADS_ + h) * DH_ * N_;
#pragma unroll
        for (int a = 0; a < 4; a++) {
            int d = ty * 4 + a;
            float4 v0 = make_float4(acc[a][0], acc[a][1], acc[a][2], acc[a][3]);
            float4 v1 = make_float4(acc[a][4], acc[a][5], acc[a][6], acc[a][7]);
            *(float4*)(dst + d * N_ + n0 + tx * 8)     = v0;
            *(float4*)(dst + d * N_ + n0 + tx * 8 + 4) = v1;
        }
    } else {
        // stage to smem, then write [n][d] with coalesced rows
#pragma unroll
        for (int a = 0; a < 4; a++)
#pragma unroll
            for (int c = 0; c < 8; c++) St[ty * 4 + a][tx * 8 + c] = acc[a][c];
        __syncthreads();
        float* dst = g_V + ((b * HEADS_ + h) * N_ + n0) * DH_;
#pragma unroll
        for (int r = 0; r < 8; r++) {
            int f = tid + r * 256;
            int nl = f >> 4, dd = (f & 15) << 2;
            float4 v = make_float4(St[dd][nl], St[dd + 1][nl], St[dd + 2][nl], St[dd + 3][nl]);
            *(float4*)(dst + nl * DH_ + dd) = v;
        }
    }
}

// ================= kernel 2: gate MLP -> k_dyn =================
__global__ __launch_bounds__(128) void gate_kernel(const float* __restrict__ x,
                                                   const float* __restrict__ w1,
                                                   const float* __restrict__ b1,
                                                   const float* __restrict__ w2,
                                                   const float* __restrict__ b2) {
    __shared__ float Xs[512][17];
    __shared__ float T1s[128][17];
    int n0 = blockIdx.x * 16;
    int b  = blockIdx.y;
    int tid = threadIdx.x;
    const float* xb = x + b * C_ * N_;
#pragma unroll 8
    for (int r = 0; r < 64; r++) {
        int f = tid + r * 128;
        int c = f >> 4, nn = f & 15;
        Xs[c][nn] = xb[c * N_ + n0 + nn];
    }
    __syncthreads();
    int nn = tid & 15, ob = tid >> 4;
    for (int rep = 0; rep < 16; rep++) {
        int o = ob + rep * 8;
        float acc = b1[o];
        const float* wr = w1 + o * 512;
        for (int c = 0; c < 512; c += 4) {
            float4 wv = *(const float4*)(wr + c);
            acc += wv.x * Xs[c][nn] + wv.y * Xs[c + 1][nn]
                 + wv.z * Xs[c + 2][nn] + wv.w * Xs[c + 3][nn];
        }
        T1s[o][nn] = fmaxf(acc, 0.f);
    }
    __syncthreads();
    if (tid < 16) {
        float s = b2[0];
        for (int o = 0; o < 128; o++) s += w2[o] * T1s[o][tid];
        float tau = 1.f / (1.f + expf(-s));
        int kd = (int)(tau * 32.f);          // trunc toward zero, matches astype(int32)
        kd = kd < 4 ? 4 : (kd > 32 ? 32 : kd);
        g_kdyn[b * N_ + n0 + tid] = kd;
    }
}

// ================= kernel 3: fused KNN attention =================
// per block: 64 queries of one (b,h); stream keys in chunks of 128;
// warp w owns queries w*8..w*8+7, top-32 one-entry-per-lane.
__global__ __launch_bounds__(256) void attn_kernel() {
    extern __shared__ float sm[];
    float* QT = sm;                 // [64][68]   (d-major)
    float* KT = sm + 64 * 68;       // [64][132]  (d-major)
    float* S  = KT + 64 * 132;      // [64][132]
    float* OS = QT;                 // alias: out tile [64 i][68], used after streaming

    int i0 = blockIdx.x * 64;
    int h  = blockIdx.y;
    int b  = blockIdx.z;
    int tid = threadIdx.x;
    int lane = tid & 31;
    int wrp  = tid >> 5;
    int bh = b * HEADS_ + h;
    const float* Qg = g_Q + bh * DH_ * N_;
    const float* Kg = g_K + bh * DH_ * N_;
    const float* Vg = g_V + bh * N_ * DH_;

    // load Q tile (straight copy: both are d-major)
#pragma unroll
    for (int r = 0; r < 4; r++) {
        int f = tid + r * 256;
        int d = f >> 4, i4 = (f & 15) << 2;
        *(float4*)&QT[d * 68 + i4] = *(const float4*)(Qg + d * N_ + i0 + i4);
    }

    float tv[8]; int tix[8]; float thr[8];
#pragma unroll
    for (int q = 0; q < 8; q++) { tv[q] = -INFINITY; tix[q] = 0; thr[q] = -INFINITY; }

    int ty = tid >> 4, tx = tid & 15;

    for (int j0 = 0; j0 < N_; j0 += 128) {
        __syncthreads();   // prev topk done (also covers initial QT load)
#pragma unroll
        for (int r = 0; r < 8; r++) {
            int f = tid + r * 256;
            int d = f >> 5, j4 = (f & 31) << 2;
            *(float4*)&KT[d * 132 + j4] = *(const float4*)(Kg + d * N_ + j0 + j4);
        }
        __syncthreads();

        float acc[4][8];
#pragma unroll
        for (int a = 0; a < 4; a++)
#pragma unroll
            for (int c = 0; c < 8; c++) acc[a][c] = 0.f;
#pragma unroll 8
        for (int d = 0; d < 64; d++) {
            float4 qv = *(float4*)&QT[d * 68 + ty * 4];
            float4 k0 = *(float4*)&KT[d * 132 + tx * 8];
            float4 k1 = *(float4*)&KT[d * 132 + tx * 8 + 4];
            float qr[4] = {qv.x, qv.y, qv.z, qv.w};
            float kr[8] = {k0.x, k0.y, k0.z, k0.w, k1.x, k1.y, k1.z, k1.w};
#pragma unroll
            for (int a = 0; a < 4; a++)
#pragma unroll
                for (int c = 0; c < 8; c++) acc[a][c] += qr[a] * kr[c];
        }
#pragma unroll
        for (int a = 0; a < 4; a++) {
            *(float4*)&S[(ty * 4 + a) * 132 + tx * 8]     = make_float4(acc[a][0], acc[a][1], acc[a][2], acc[a][3]);
            *(float4*)&S[(ty * 4 + a) * 132 + tx * 8 + 4] = make_float4(acc[a][4], acc[a][5], acc[a][6], acc[a][7]);
        }
        __syncthreads();

        // streaming top-32 update (raw scores; scale is monotone, applied later)
#pragma unroll
        for (int q = 0; q < 8; q++) {
            int il = wrp * 8 + q;
            float th = thr[q];
            for (int hh = 0; hh < 4; hh++) {
                float s = S[il * 132 + hh * 32 + lane];
                unsigned m = __ballot_sync(FULL, s > th);
                while (m) {
                    int src = __ffs(m) - 1; m &= m - 1;
                    float vn = __shfl_sync(FULL, s, src);
                    if (!(vn > th)) continue;   // threshold rose meanwhile
                    int jn = j0 + hh * 32 + src;
                    // evict min value; among ties evict the LARGEST index
                    unsigned long long key =
                        ((unsigned long long)ordf(tv[q]) << 32) |
                        (unsigned)(((4095 - tix[q]) << 5) | lane);
#pragma unroll
                    for (int o = 16; o; o >>= 1) {
                        unsigned long long k2 = __shfl_xor_sync(FULL, key, o);
                        key = k2 < key ? k2 : key;
                    }
                    int ml = (int)(key & 31u);
                    if (lane == ml) { tv[q] = vn; tix[q] = jn; }
                    float t = tv[q];
#pragma unroll
                    for (int o = 16; o; o >>= 1) t = fminf(t, __shfl_xor_sync(FULL, t, o));
                    th = t;
                }
            }
            thr[q] = th;
        }
    }
    __syncthreads();   // streaming done; QT (aliased as OS) is free

    // finalize: sort, masked softmax over first k_dyn, gather V
#pragma unroll 1
    for (int q = 0; q < 8; q++) {
        int il = wrp * 8 + q;
        int ig = i0 + il;
        // key ascending == value descending, ties by ascending index (jax top_k order)
        unsigned long long key =
            ((unsigned long long)(~ordf(tv[q])) << 32) | (unsigned)tix[q];
#pragma unroll
        for (int k = 2; k <= 32; k <<= 1) {
#pragma unroll
            for (int j = k >> 1; j > 0; j >>= 1) {
                unsigned long long partner = __shfl_xor_sync(FULL, key, j);
                bool dirAsc = ((lane & k) == 0);
                bool lower  = ((lane & j) == 0);
                unsigned long long mn = key < partner ? key : partner;
                unsigned long long mx = key < partner ? partner : key;
                key = (lower == dirAsc) ? mn : mx;
            }
        }
        float val = iordf(~(unsigned)(key >> 32));
        int   idx = (int)(key & 0xffffffffull);

        int kd = g_kdyn[b * N_ + ig];
        float sv = val * 0.125f;                      // 1/sqrt(64)
        float mx = __shfl_sync(FULL, sv, 0);          // rank-0 max (always kept)
        float e  = (lane < kd) ? expf(sv - mx) : 0.f;
        float ssum = e;
#pragma unroll
        for (int o = 16; o; o >>= 1) ssum += __shfl_xor_sync(FULL, ssum, o);
        float wt = e / ssum;

        const float* vrow = Vg + idx * DH_;
        bool act = lane < kd;
#pragma unroll 4
        for (int t4 = 0; t4 < 16; t4++) {
            float4 vv = act ? *(const float4*)(vrow + t4 * 4) : make_float4(0.f, 0.f, 0.f, 0.f);
            float4 p = make_float4(wt * vv.x, wt * vv.y, wt * vv.z, wt * vv.w);
#pragma unroll
            for (int o = 16; o; o >>= 1) {
                p.x += __shfl_xor_sync(FULL, p.x, o);
                p.y += __shfl_xor_sync(FULL, p.y, o);
                p.z += __shfl_xor_sync(FULL, p.z, o);
                p.w += __shfl_xor_sync(FULL, p.w, o);
            }
            if (lane == 0) *(float4*)&OS[il * 68 + t4 * 4] = p;
        }
    }
    __syncthreads();

    // write OS -> g_A[b][h*64+d][i0..i0+63] (coalesced in i)
    float* Ab = g_A + (b * C_ + h * 64) * N_;
#pragma unroll
    for (int r = 0; r < 4; r++) {
        int f = tid + r * 256;
        int d = f >> 4, i4 = (f & 15) << 2;
        float4 v = make_float4(OS[(i4 + 0) * 68 + d], OS[(i4 + 1) * 68 + d],
                               OS[(i4 + 2) * 68 + d], OS[(i4 + 3) * 68 + d]);
        *(float4*)(Ab + d * N_ + i0 + i4) = v;
    }
}

// ================= kernel 4: proj GEMM + bias + residual =================
__global__ __launch_bounds__(256) void proj_kernel(const float* __restrict__ x,
                                                   const float* __restrict__ w,
                                                   const float* __restrict__ bias,
                                                   float* __restrict__ out) {
    __shared__ float Ws[16][68];
    __shared__ float As[16][132];
    int n0 = blockIdx.x * 128;
    int o0 = blockIdx.y * 64;
    int b  = blockIdx.z;
    int tid = threadIdx.x;
    int ty = tid >> 4, tx = tid & 15;
    const float* Ab = g_A + b * C_ * N_;

    float acc[4][8];
#pragma unroll
    for (int a = 0; a < 4; a++)
#pragma unroll
        for (int c = 0; c < 8; c++) acc[a][c] = 0.f;

    for (int c0 = 0; c0 < C_; c0 += 16) {
        {
            int oo = tid >> 2;
            int cc4 = (tid & 3) << 2;
            float4 wv = *(const float4*)(w + (o0 + oo) * C_ + c0 + cc4);
            Ws[cc4 + 0][oo] = wv.x; Ws[cc4 + 1][oo] = wv.y;
            Ws[cc4 + 2][oo] = wv.z; Ws[cc4 + 3][oo] = wv.w;
        }
#pragma unroll
        for (int r = 0; r < 2; r++) {
            int f = tid + r * 256;
            int cc = f >> 5, n4 = (f & 31) << 2;
            *(float4*)&As[cc][n4] = *(const float4*)(Ab + (c0 + cc) * N_ + n0 + n4);
        }
        __syncthreads();
#pragma unroll
        for (int cc = 0; cc < 16; cc++) {
            float4 wv = *(float4*)&Ws[cc][ty * 4];
            float4 a0 = *(float4*)&As[cc][tx * 8];
            float4 a1 = *(float4*)&As[cc][tx * 8 + 4];
            float wr[4] = {wv.x, wv.y, wv.z, wv.w};
            float ar[8] = {a0.x, a0.y, a0.z, a0.w, a1.x, a1.y, a1.z, a1.w};
#pragma unroll
            for (int a = 0; a < 4; a++)
#pragma unroll
                for (int c = 0; c < 8; c++) acc[a][c] += wr[a] * ar[c];
        }
        __syncthreads();
    }

    const float* xb = x + b * C_ * N_;
    float* ob = out + b * C_ * N_;
#pragma unroll
    for (int a = 0; a < 4; a++) {
        int o = o0 + ty * 4 + a;
        float bs = bias[o];
        float4 x0 = *(const float4*)(xb + o * N_ + n0 + tx * 8);
        float4 x1 = *(const float4*)(xb + o * N_ + n0 + tx * 8 + 4);
        float4 r0 = make_float4(x0.x + bs + acc[a][0], x0.y + bs + acc[a][1],
                                x0.z + bs + acc[a][2], x0.w + bs + acc[a][3]);
        float4 r1 = make_float4(x1.x + bs + acc[a][4], x1.y + bs + acc[a][5],
                                x1.z + bs + acc[a][6], x1.w + bs + acc[a][7]);
        *(float4*)(ob + o * N_ + n0 + tx * 8)     = r0;
        *(float4*)(ob + o * N_ + n0 + tx * 8 + 4) = r1;
    }
}

// ================= launch =================
extern "C" void kernel_launch(void* const* d_in, const int* in_sizes, int n_in,
                              void* d_out, int out_size) {
    const float* x      = (const float*)d_in[0];
    const float* w_qkv  = (const float*)d_in[1];
    const float* w_proj = (const float*)d_in[2];
    const float* b_proj = (const float*)d_in[3];
    const float* w_g1   = (const float*)d_in[4];
    const float* b_g1   = (const float*)d_in[5];
    const float* w_g2   = (const float*)d_in[6];
    const float* b_g2   = (const float*)d_in[7];
    float* out = (float*)d_out;

    qkv_gemm_kernel<<<dim3(N_ / 128, (3 * C_) / 64, B_), 256>>>(x, w_qkv);
    gate_kernel<<<dim3(N_ / 16, B_), 128>>>(x, w_g1, b_g1, w_g2, b_g2);

    const int attn_smem = (64 * 68 + 64 * 132 + 64 * 132) * (int)sizeof(float);  // 84992 B
    cudaFuncSetAttribute(attn_kernel, cudaFuncAttributeMaxDynamicSharedMemorySize, attn_smem);
    attn_kernel<<<dim3(N_ / 64, HEADS_, B_), 256, attn_smem>>>();

    proj_kernel<<<dim3(N_ / 128, C_ / 64, B_), 256>>>(x, w_proj, b_proj, out);
}

// round 6
// speedup vs baseline: 3.1346x; 3.1346x over previous
#include <cuda_runtime.h>
#include <math.h>

#define FULL 0xffffffffu
#define B_     2
#define C_     512
#define N_     4096
#define HEADS_ 8
#define DH_    64
#define KMAX_  32

// ---------------- scratch (device globals; no allocation allowed) ----------------
__device__ float g_Q[B_ * HEADS_ * DH_ * N_];   // [b][h][d][n]
__device__ float g_K[B_ * HEADS_ * DH_ * N_];   // [b][h][d][n]
__device__ float g_V[B_ * HEADS_ * N_ * DH_];   // [b][h][n][d]
__device__ float g_A[B_ * C_ * N_];             // attention out, [b][c][n], c = h*64+d
__device__ int   g_kdyn[B_ * N_];

// ---------------- helpers ----------------
__device__ __forceinline__ unsigned ordf(float v) {
    unsigned u = __float_as_uint(v);
    return (u & 0x80000000u) ? ~u : (u | 0x80000000u);
}
__device__ __forceinline__ float iordf(unsigned o) {
    unsigned u = (o & 0x80000000u) ? (o & 0x7fffffffu) : ~o;
    return __uint_as_float(u);
}

// ================= kernel 1: QKV GEMM =================
__global__ __launch_bounds__(256) void qkv_gemm_kernel(const float* __restrict__ x,
                                                       const float* __restrict__ w) {
    __shared__ float Ws[16][68];
    __shared__ float Xs[16][132];
    __shared__ float St[64][132];
    int n0 = blockIdx.x * 128;
    int o0 = blockIdx.y * 64;
    int b  = blockIdx.z;
    int tid = threadIdx.x;
    int ty = tid >> 4, tx = tid & 15;
    const float* xb = x + b * C_ * N_;

    float acc[4][8];
#pragma unroll
    for (int a = 0; a < 4; a++)
#pragma unroll
        for (int c = 0; c < 8; c++) acc[a][c] = 0.f;

    for (int c0 = 0; c0 < C_; c0 += 16) {
        {   // W tile transpose-load: Ws[cc][oo]
            int oo = tid >> 2;
            int cc4 = (tid & 3) << 2;
            float4 wv = *(const float4*)(w + (o0 + oo) * C_ + c0 + cc4);
            Ws[cc4 + 0][oo] = wv.x; Ws[cc4 + 1][oo] = wv.y;
            Ws[cc4 + 2][oo] = wv.z; Ws[cc4 + 3][oo] = wv.w;
        }
#pragma unroll
        for (int r = 0; r < 2; r++) {   // X tile: Xs[cc][nn]
            int f = tid + r * 256;
            int cc = f >> 5, n4 = (f & 31) << 2;
            *(float4*)&Xs[cc][n4] = *(const float4*)(xb + (c0 + cc) * N_ + n0 + n4);
        }
        __syncthreads();
#pragma unroll
        for (int cc = 0; cc < 16; cc++) {
            float4 wv = *(float4*)&Ws[cc][ty * 4];
            float4 x0 = *(float4*)&Xs[cc][tx * 8];
            float4 x1 = *(float4*)&Xs[cc][tx * 8 + 4];
            float wr[4] = {wv.x, wv.y, wv.z, wv.w};
            float xr[8] = {x0.x, x0.y, x0.z, x0.w, x1.x, x1.y, x1.z, x1.w};
#pragma unroll
            for (int a = 0; a < 4; a++)
#pragma unroll
                for (int c = 0; c < 8; c++) acc[a][c] += wr[a] * xr[c];
        }
        __syncthreads();
    }

    int sel = o0 >> 9;            // 0:Q 1:K 2:V
    int h   = (o0 & 511) >> 6;
    if (sel < 2) {
        float* dst = (sel == 0 ? g_Q : g_K) + (b * HEADS_ + h) * DH_ * N_;
#pragma unroll
        for (int a = 0; a < 4; a++) {
            int d = ty * 4 + a;
            float4 v0 = make_float4(acc[a][0], acc[a][1], acc[a][2], acc[a][3]);
            float4 v1 = make_float4(acc[a][4], acc[a][5], acc[a][6], acc[a][7]);
            *(float4*)(dst + d * N_ + n0 + tx * 8)     = v0;
            *(float4*)(dst + d * N_ + n0 + tx * 8 + 4) = v1;
        }
    } else {
#pragma unroll
        for (int a = 0; a < 4; a++)
#pragma unroll
            for (int c = 0; c < 8; c++) St[ty * 4 + a][tx * 8 + c] = acc[a][c];
        __syncthreads();
        float* dst = g_V + ((b * HEADS_ + h) * N_ + n0) * DH_;
#pragma unroll
        for (int r = 0; r < 8; r++) {
            int f = tid + r * 256;
            int nl = f >> 4, dd = (f & 15) << 2;
            float4 v = make_float4(St[dd][nl], St[dd + 1][nl], St[dd + 2][nl], St[dd + 3][nl]);
            *(float4*)(dst + nl * DH_ + dd) = v;
        }
    }
}

// ================= kernel 2: gate MLP -> k_dyn =================
__global__ __launch_bounds__(128) void gate_kernel(const float* __restrict__ x,
                                                   const float* __restrict__ w1,
                                                   const float* __restrict__ b1,
                                                   const float* __restrict__ w2,
                                                   const float* __restrict__ b2) {
    __shared__ float Xs[512][17];
    __shared__ float T1s[128][17];
    int n0 = blockIdx.x * 16;
    int b  = blockIdx.y;
    int tid = threadIdx.x;
    const float* xb = x + b * C_ * N_;
#pragma unroll 8
    for (int r = 0; r < 64; r++) {
        int f = tid + r * 128;
        int c = f >> 4, nn = f & 15;
        Xs[c][nn] = xb[c * N_ + n0 + nn];
    }
    __syncthreads();
    int nn = tid & 15, ob = tid >> 4;
    for (int rep = 0; rep < 16; rep++) {
        int o = ob + rep * 8;
        float acc = b1[o];
        const float* wr = w1 + o * 512;
        for (int c = 0; c < 512; c += 4) {
            float4 wv = *(const float4*)(wr + c);
            acc += wv.x * Xs[c][nn] + wv.y * Xs[c + 1][nn]
                 + wv.z * Xs[c + 2][nn] + wv.w * Xs[c + 3][nn];
        }
        T1s[o][nn] = fmaxf(acc, 0.f);
    }
    __syncthreads();
    // 2nd layer: warp w (0..3) handles 8 pixels; lanes split the 128-dim dot 4-way
    if (tid < 128) {
        int nn2 = (tid >> 3) & 15;        // wait: need 16 pixels over 128 threads
    }
    {
        // thread t handles pixel p = t>>3, 16 channels each (t&7)*16..+15
        int p = tid >> 3;                 // 0..15
        int seg = tid & 7;                // 0..7
        float s = 0.f;
        const float* wv = w2 + seg * 16;
        const float* tc = &T1s[seg * 16][0];
        for (int o = 0; o < 16; o++) s += wv[o] * T1s[seg * 16 + o][p];
#pragma unroll
        for (int o = 4; o; o >>= 1) s += __shfl_xor_sync(FULL, s, o);
        if (seg == 0) {
            s += b2[0];
            float tau = 1.f / (1.f + expf(-s));
            int kd = (int)(tau * 32.f);
            kd = kd < 4 ? 4 : (kd > 32 ? 32 : kd);
            g_kdyn[b * N_ + n0 + p] = kd;
        }
    }
}

// ================= kernel 3: fused KNN attention =================
// 512 threads; warp w owns queries w*4..w*4+3 of a 64-query tile.
// Per 128-key chunk: warp computes its own 4x128 scores (lane owns j=4*lane..4*lane+3),
// streaming top-32 with redux-based O(1) insertion.
__global__ __launch_bounds__(512) void attn_kernel() {
    extern __shared__ float sm[];
    float* QT = sm;                  // [64 d][68]  QT[d*68+i]
    float* KT = sm + 64 * 68;        // [64 d][132] KT[d*132+j]
    float* Wsm = sm;                 // alias (after streaming): [64 i][33] weights
    int*   Ism = (int*)(sm + 64 * 68); // alias: [64 i][33] indices

    int i0 = blockIdx.x * 64;
    int h  = blockIdx.y;
    int b  = blockIdx.z;
    int tid = threadIdx.x;
    int lane = tid & 31;
    int wrp  = tid >> 5;            // 0..15
    int bh = b * HEADS_ + h;
    const float* Qg = g_Q + bh * DH_ * N_;
    const float* Kg = g_K + bh * DH_ * N_;
    const float* Vg = g_V + bh * N_ * DH_;

    // load Q tile
#pragma unroll
    for (int r = 0; r < 2; r++) {
        int f = tid + r * 512;
        int d = f >> 4, i4 = (f & 15) << 2;
        *(float4*)&QT[d * 68 + i4] = *(const float4*)(Qg + d * N_ + i0 + i4);
    }

    float tv[4]; int tix[4]; float th[4];
#pragma unroll
    for (int q = 0; q < 4; q++) { tv[q] = -INFINITY; tix[q] = 0; th[q] = -INFINITY; }

    const float* qbase = QT + wrp * 4;

    for (int j0 = 0; j0 < N_; j0 += 128) {
        __syncthreads();   // prev GEMM done reading KT (and covers initial QT load)
#pragma unroll
        for (int r = 0; r < 4; r++) {
            int f = tid + r * 512;
            int d = f >> 5, j4 = (f & 31) << 2;
            *(float4*)&KT[d * 132 + j4] = *(const float4*)(Kg + d * N_ + j0 + j4);
        }
        __syncthreads();

        // scores: acc[q][slot], j = 4*lane + slot
        float acc[4][4];
#pragma unroll
        for (int q = 0; q < 4; q++)
#pragma unroll
            for (int s = 0; s < 4; s++) acc[q][s] = 0.f;
#pragma unroll 8
        for (int d = 0; d < 64; d++) {
            float4 qv = *(const float4*)(qbase + d * 68);          // broadcast
            float4 kv = *(const float4*)(&KT[d * 132 + lane * 4]); // conflict-free
            float qr[4] = {qv.x, qv.y, qv.z, qv.w};
            float kr[4] = {kv.x, kv.y, kv.z, kv.w};
#pragma unroll
            for (int q = 0; q < 4; q++)
#pragma unroll
                for (int s = 0; s < 4; s++) acc[q][s] += qr[q] * kr[s];
        }

        // streaming top-32 update (register scores, redux-based insertion)
#pragma unroll
        for (int q = 0; q < 4; q++) {
            float lmax = fmaxf(fmaxf(acc[q][0], acc[q][1]), fmaxf(acc[q][2], acc[q][3]));
            unsigned m = __ballot_sync(FULL, lmax > th[q]);
            while (m) {
                int src = __ffs(m) - 1; m &= m - 1;
                float v0 = __shfl_sync(FULL, acc[q][0], src);
                float v1 = __shfl_sync(FULL, acc[q][1], src);
                float v2 = __shfl_sync(FULL, acc[q][2], src);
                float v3 = __shfl_sync(FULL, acc[q][3], src);
                float vs[4] = {v0, v1, v2, v3};
#pragma unroll
                for (int s = 0; s < 4; s++) {
                    float vn = vs[s];
                    if (vn > th[q]) {          // warp-uniform (vn broadcast, th uniform)
                        int jn = j0 + (src << 2) + s;
                        // evict: lane holding current min; among value-ties, largest index
                        unsigned tied = __ballot_sync(FULL, tv[q] == th[q]);
                        int ml;
                        if (__popc(tied) > 1) {
                            unsigned key = ((tied >> lane) & 1u)
                                         ? (((unsigned)tix[q] << 5) | lane) : 0u;
                            ml = (int)(__reduce_max_sync(FULL, key) & 31u);
                        } else {
                            ml = __ffs(tied) - 1;
                        }
                        if (lane == ml) { tv[q] = vn; tix[q] = jn; }
                        th[q] = iordf(__reduce_min_sync(FULL, ordf(tv[q])));
                    }
                }
            }
        }
    }
    __syncthreads();   // all warps done with QT/KT; safe to alias

    // finalize: sort, masked softmax, write (wt, idx) tables
    int kd4[4];
#pragma unroll
    for (int q = 0; q < 4; q++) kd4[q] = g_kdyn[b * N_ + i0 + wrp * 4 + q];

#pragma unroll 1
    for (int q = 0; q < 4; q++) {
        int il = wrp * 4 + q;
        unsigned long long key =
            ((unsigned long long)(~ordf(tv[q])) << 32) | (unsigned)tix[q];
#pragma unroll
        for (int k = 2; k <= 32; k <<= 1) {
#pragma unroll
            for (int j = k >> 1; j > 0; j >>= 1) {
                unsigned long long partner = __shfl_xor_sync(FULL, key, j);
                bool dirAsc = ((lane & k) == 0);
                bool lower  = ((lane & j) == 0);
                unsigned long long mn = key < partner ? key : partner;
                unsigned long long mx = key < partner ? partner : key;
                key = (lower == dirAsc) ? mn : mx;
            }
        }
        float val = iordf(~(unsigned)(key >> 32));
        int   idx = (int)(key & 0xffffffffull);

        int kd = kd4[q];
        float sv = val * 0.125f;                    // 1/sqrt(64)
        float mx = __shfl_sync(FULL, sv, 0);
        float e  = (lane < kd) ? expf(sv - mx) : 0.f;
        float ssum = e;
#pragma unroll
        for (int o = 16; o; o >>= 1) ssum += __shfl_xor_sync(FULL, ssum, o);
        float wt = e / ssum;

        Wsm[il * 33 + lane] = wt;
        Ism[il * 33 + lane] = idx;
    }
    __syncthreads();

    // gather: thread = (i = tid&63, dq = tid>>6 -> 8 d's); coalesced STG per warp
    {
        int i  = tid & 63;
        int dq = tid >> 6;
        const float* Wr = &Wsm[i * 33];
        const int*   Ir = &Ism[i * 33];
        float4 o0 = make_float4(0.f, 0.f, 0.f, 0.f);
        float4 o1 = make_float4(0.f, 0.f, 0.f, 0.f);
#pragma unroll 4
        for (int k = 0; k < 32; k++) {
            float wv = Wr[k];
            int   ix = Ir[k];
            const float* vrow = Vg + ix * DH_ + dq * 8;
            float4 a = *(const float4*)(vrow);
            float4 c = *(const float4*)(vrow + 4);
            o0.x += wv * a.x; o0.y += wv * a.y; o0.z += wv * a.z; o0.w += wv * a.w;
            o1.x += wv * c.x; o1.y += wv * c.y; o1.z += wv * c.z; o1.w += wv * c.w;
        }
        float* Ab = g_A + (b * C_ + h * 64) * N_ + i0 + i;
        float ov[8] = {o0.x, o0.y, o0.z, o0.w, o1.x, o1.y, o1.z, o1.w};
#pragma unroll
        for (int s = 0; s < 8; s++) {
            int d = dq * 8 + s;
            Ab[d * N_] = ov[s];
        }
    }
}

// ================= kernel 4: proj GEMM + bias + residual =================
__global__ __launch_bounds__(256) void proj_kernel(const float* __restrict__ x,
                                                   const float* __restrict__ w,
                                                   const float* __restrict__ bias,
                                                   float* __restrict__ out) {
    __shared__ float Ws[16][68];
    __shared__ float As[16][132];
    int n0 = blockIdx.x * 128;
    int o0 = blockIdx.y * 64;
    int b  = blockIdx.z;
    int tid = threadIdx.x;
    int ty = tid >> 4, tx = tid & 15;
    const float* Ab = g_A + b * C_ * N_;

    float acc[4][8];
#pragma unroll
    for (int a = 0; a < 4; a++)
#pragma unroll
        for (int c = 0; c < 8; c++) acc[a][c] = 0.f;

    for (int c0 = 0; c0 < C_; c0 += 16) {
        {
            int oo = tid >> 2;
            int cc4 = (tid & 3) << 2;
            float4 wv = *(const float4*)(w + (o0 + oo) * C_ + c0 + cc4);
            Ws[cc4 + 0][oo] = wv.x; Ws[cc4 + 1][oo] = wv.y;
            Ws[cc4 + 2][oo] = wv.z; Ws[cc4 + 3][oo] = wv.w;
        }
#pragma unroll
        for (int r = 0; r < 2; r++) {
            int f = tid + r * 256;
            int cc = f >> 5, n4 = (f & 31) << 2;
            *(float4*)&As[cc][n4] = *(const float4*)(Ab + (c0 + cc) * N_ + n0 + n4);
        }
        __syncthreads();
#pragma unroll
        for (int cc = 0; cc < 16; cc++) {
            float4 wv = *(float4*)&Ws[cc][ty * 4];
            float4 a0 = *(float4*)&As[cc][tx * 8];
            float4 a1 = *(float4*)&As[cc][tx * 8 + 4];
            float wr[4] = {wv.x, wv.y, wv.z, wv.w};
            float ar[8] = {a0.x, a0.y, a0.z, a0.w, a1.x, a1.y, a1.z, a1.w};
#pragma unroll
            for (int a = 0; a < 4; a++)
#pragma unroll
                for (int c = 0; c < 8; c++) acc[a][c] += wr[a] * ar[c];
        }
        __syncthreads();
    }

    const float* xb = x + b * C_ * N_;
    float* ob = out + b * C_ * N_;
#pragma unroll
    for (int a = 0; a < 4; a++) {
        int o = o0 + ty * 4 + a;
        float bs = bias[o];
        float4 x0 = *(const float4*)(xb + o * N_ + n0 + tx * 8);
        float4 x1 = *(const float4*)(xb + o * N_ + n0 + tx * 8 + 4);
        float4 r0 = make_float4(x0.x + bs + acc[a][0], x0.y + bs + acc[a][1],
                                x0.z + bs + acc[a][2], x0.w + bs + acc[a][3]);
        float4 r1 = make_float4(x1.x + bs + acc[a][4], x1.y + bs + acc[a][5],
                                x1.z + bs + acc[a][6], x1.w + bs + acc[a][7]);
        *(float4*)(ob + o * N_ + n0 + tx * 8)     = r0;
        *(float4*)(ob + o * N_ + n0 + tx * 8 + 4) = r1;
    }
}

// ================= launch =================
extern "C" void kernel_launch(void* const* d_in, const int* in_sizes, int n_in,
                              void* d_out, int out_size) {
    const float* x      = (const float*)d_in[0];
    const float* w_qkv  = (const float*)d_in[1];
    const float* w_proj = (const float*)d_in[2];
    const float* b_proj = (const float*)d_in[3];
    const float* w_g1   = (const float*)d_in[4];
    const float* b_g1   = (const float*)d_in[5];
    const float* w_g2   = (const float*)d_in[6];
    const float* b_g2   = (const float*)d_in[7];
    float* out = (float*)d_out;

    qkv_gemm_kernel<<<dim3(N_ / 128, (3 * C_) / 64, B_), 256>>>(x, w_qkv);
    gate_kernel<<<dim3(N_ / 16, B_), 128>>>(x, w_g1, b_g1, w_g2, b_g2);

    const int attn_smem = (64 * 68 + 64 * 132) * (int)sizeof(float);  // 51200 B
    cudaFuncSetAttribute(attn_kernel, cudaFuncAttributeMaxDynamicSharedMemorySize, attn_smem);
    attn_kernel<<<dim3(N_ / 64, HEADS_, B_), 512, attn_smem>>>();

    proj_kernel<<<dim3(N_ / 128, C_ / 64, B_), 256>>>(x, w_proj, b_proj, out);
}

// round 10
// speedup vs baseline: 3.3427x; 1.0664x over previous
#include <cuda_runtime.h>
#include <math.h>

#define FULL 0xffffffffu
#define B_     2
#define C_     512
#define N_     4096
#define HEADS_ 8
#define DH_    64
#define KMAX_  32

typedef unsigned long long u64;

// ---------------- scratch (device globals; no allocation allowed) ----------------
__device__ float g_Q[B_ * HEADS_ * DH_ * N_];   // [b][h][d][n]
__device__ float g_K[B_ * HEADS_ * DH_ * N_];   // [b][h][d][n]
__device__ float g_V[B_ * HEADS_ * N_ * DH_];   // [b][h][n][d]
__device__ float g_A[B_ * C_ * N_];             // attention out, [b][c][n]
__device__ int   g_kdyn[B_ * N_];

// ---------------- helpers ----------------
__device__ __forceinline__ unsigned ordf(float v) {
    unsigned u = __float_as_uint(v);
    return (u & 0x80000000u) ? ~u : (u | 0x80000000u);
}
__device__ __forceinline__ float iordf(unsigned o) {
    unsigned u = (o & 0x80000000u) ? (o & 0x7fffffffu) : ~o;
    return __uint_as_float(u);
}
__device__ __forceinline__ u64 pk2(float lo, float hi) {
    u64 r; asm("mov.b64 %0,{%1,%2};" : "=l"(r) : "f"(lo), "f"(hi)); return r;
}
__device__ __forceinline__ void fma2(u64& d, u64 a, u64 b) {
    asm("fma.rn.f32x2 %0,%1,%2,%0;" : "+l"(d) : "l"(a), "l"(b));
}
__device__ __forceinline__ float2 upk2(u64 v) {
    float2 f; asm("mov.b64 {%0,%1},%2;" : "=f"(f.x), "=f"(f.y) : "l"(v)); return f;
}

// ================= kernel 1: QKV GEMM (packed FFMA2) =================
__global__ __launch_bounds__(256) void qkv_gemm_kernel(const float* __restrict__ x,
                                                       const float* __restrict__ w) {
    __shared__ float Ws[16][68];
    __shared__ float Xs[16][132];
    __shared__ float St[64][132];
    int n0 = blockIdx.x * 128;
    int o0 = blockIdx.y * 64;
    int b  = blockIdx.z;
    int tid = threadIdx.x;
    int ty = tid >> 4, tx = tid & 15;
    const float* xb = x + b * C_ * N_;

    u64 accp[4][4];
#pragma unroll
    for (int a = 0; a < 4; a++)
#pragma unroll
        for (int c = 0; c < 4; c++) accp[a][c] = 0ull;

    for (int c0 = 0; c0 < C_; c0 += 16) {
        {   // W tile transpose-load: Ws[cc][oo]
            int oo = tid >> 2;
            int cc4 = (tid & 3) << 2;
            float4 wv = *(const float4*)(w + (o0 + oo) * C_ + c0 + cc4);
            Ws[cc4 + 0][oo] = wv.x; Ws[cc4 + 1][oo] = wv.y;
            Ws[cc4 + 2][oo] = wv.z; Ws[cc4 + 3][oo] = wv.w;
        }
#pragma unroll
        for (int r = 0; r < 2; r++) {   // X tile
            int f = tid + r * 256;
            int cc = f >> 5, n4 = (f & 31) << 2;
            *(float4*)&Xs[cc][n4] = *(const float4*)(xb + (c0 + cc) * N_ + n0 + n4);
        }
        __syncthreads();
#pragma unroll
        for (int cc = 0; cc < 16; cc++) {
            float4 wv = *(float4*)&Ws[cc][ty * 4];
            ulonglong2 xa = *(ulonglong2*)&Xs[cc][tx * 8];
            ulonglong2 xb2 = *(ulonglong2*)&Xs[cc][tx * 8 + 4];
            u64 wd[4] = {pk2(wv.x, wv.x), pk2(wv.y, wv.y), pk2(wv.z, wv.z), pk2(wv.w, wv.w)};
#pragma unroll
            for (int a = 0; a < 4; a++) {
                fma2(accp[a][0], wd[a], xa.x);
                fma2(accp[a][1], wd[a], xa.y);
                fma2(accp[a][2], wd[a], xb2.x);
                fma2(accp[a][3], wd[a], xb2.y);
            }
        }
        __syncthreads();
    }

    float acc[4][8];
#pragma unroll
    for (int a = 0; a < 4; a++)
#pragma unroll
        for (int c = 0; c < 4; c++) {
            float2 f = upk2(accp[a][c]);
            acc[a][2 * c] = f.x; acc[a][2 * c + 1] = f.y;
        }

    int sel = o0 >> 9;            // 0:Q 1:K 2:V
    int h   = (o0 & 511) >> 6;
    if (sel < 2) {
        float* dst = (sel == 0 ? g_Q : g_K) + (b * HEADS_ + h) * DH_ * N_;
#pragma unroll
        for (int a = 0; a < 4; a++) {
            int d = ty * 4 + a;
            *(float4*)(dst + d * N_ + n0 + tx * 8)     = make_float4(acc[a][0], acc[a][1], acc[a][2], acc[a][3]);
            *(float4*)(dst + d * N_ + n0 + tx * 8 + 4) = make_float4(acc[a][4], acc[a][5], acc[a][6], acc[a][7]);
        }
    } else {
#pragma unroll
        for (int a = 0; a < 4; a++)
#pragma unroll
            for (int c = 0; c < 8; c++) St[ty * 4 + a][tx * 8 + c] = acc[a][c];
        __syncthreads();
        float* dst = g_V + ((b * HEADS_ + h) * N_ + n0) * DH_;
#pragma unroll
        for (int r = 0; r < 8; r++) {
            int f = tid + r * 256;
            int nl = f >> 4, dd = (f & 15) << 2;
            float4 v = make_float4(St[dd][nl], St[dd + 1][nl], St[dd + 2][nl], St[dd + 3][nl]);
            *(float4*)(dst + nl * DH_ + dd) = v;
        }
    }
}

// ================= kernel 2: gate MLP -> k_dyn =================
__global__ __launch_bounds__(128) void gate_kernel(const float* __restrict__ x,
                                                   const float* __restrict__ w1,
                                                   const float* __restrict__ b1,
                                                   const float* __restrict__ w2,
                                                   const float* __restrict__ b2) {
    __shared__ float Xs[512][17];
    __shared__ float T1s[128][17];
    int n0 = blockIdx.x * 16;
    int b  = blockIdx.y;
    int tid = threadIdx.x;
    const float* xb = x + b * C_ * N_;
#pragma unroll 8
    for (int r = 0; r < 64; r++) {
        int f = tid + r * 128;
        int c = f >> 4, nn = f & 15;
        Xs[c][nn] = xb[c * N_ + n0 + nn];
    }
    __syncthreads();
    int nn = tid & 15, ob = tid >> 4;
    for (int rep = 0; rep < 16; rep++) {
        int o = ob + rep * 8;
        float acc = b1[o];
        const float* wr = w1 + o * 512;
        for (int c = 0; c < 512; c += 4) {
            float4 wv = *(const float4*)(wr + c);
            acc += wv.x * Xs[c][nn] + wv.y * Xs[c + 1][nn]
                 + wv.z * Xs[c + 2][nn] + wv.w * Xs[c + 3][nn];
        }
        T1s[o][nn] = fmaxf(acc, 0.f);
    }
    __syncthreads();
    {
        // thread t: pixel p = t>>3, channel segment (t&7)*16..+15
        int p = tid >> 3;
        int seg = tid & 7;
        float s = 0.f;
        for (int o = 0; o < 16; o++) s += w2[seg * 16 + o] * T1s[seg * 16 + o][p];
#pragma unroll
        for (int o = 4; o; o >>= 1) s += __shfl_xor_sync(FULL, s, o);
        if (seg == 0) {
            s += b2[0];
            float tau = 1.f / (1.f + expf(-s));
            int kd = (int)(tau * 32.f);
            kd = kd < 4 ? 4 : (kd > 32 ? 32 : kd);
            g_kdyn[b * N_ + n0 + p] = kd;
        }
    }
}

// ================= kernel 3: fused KNN attention (FFMA2 + double-buffer) =================
// 512 threads; warp w owns queries w*4..w*4+3 of a 64-query tile.
// Q,K tiles stored d-pair-interleaved (float2) so packed fp32 FMA operands load directly.
// lane owns slots j = s*32 + lane (s = 0..3) within each 128-key chunk.
__global__ __launch_bounds__(512) void attn_kernel() {
    extern __shared__ char smraw[];
    float2* Q2  = (float2*)smraw;                      // [32 d2][66]
    float2* KTb = (float2*)(smraw + 32 * 66 * 8);      // 2 x [32 d2][132]
    float*  Wsm = (float*)smraw;                       // alias after streaming: [64][33]
    int*    Ism = (int*)(smraw + 64 * 33 * 4);         // alias: [64][33]

    int i0 = blockIdx.x * 64;
    int h  = blockIdx.y;
    int b  = blockIdx.z;
    int tid = threadIdx.x;
    int lane = tid & 31;
    int wrp  = tid >> 5;            // 0..15
    int bh = b * HEADS_ + h;
    const float* Qg = g_Q + bh * DH_ * N_;
    const float* Kg = g_K + bh * DH_ * N_;
    const float* Vg = g_V + bh * N_ * DH_;

    int ld_d2 = tid >> 4;           // 0..31
    int ld_i4 = (tid & 15) << 2;    // Q: 4 i's
    int ld_j8 = (tid & 15) << 3;    // K: 8 j's

    // ---- load Q tile interleaved: Q2[d2][i] = (Q[2d2][i], Q[2d2+1][i]) ----
    {
        float4 a = *(const float4*)(Qg + (2 * ld_d2) * N_ + i0 + ld_i4);
        float4 c = *(const float4*)(Qg + (2 * ld_d2 + 1) * N_ + i0 + ld_i4);
        float2* dst = Q2 + ld_d2 * 66 + ld_i4;
        *(float4*)&dst[0] = make_float4(a.x, c.x, a.y, c.y);
        *(float4*)&dst[2] = make_float4(a.z, c.z, a.w, c.w);
    }

    // ---- prologue: load K chunk 0 into buf0 ----
    {
        const float* r0 = Kg + (2 * ld_d2) * N_ + ld_j8;
        const float* r1 = Kg + (2 * ld_d2 + 1) * N_ + ld_j8;
        float4 a0 = *(const float4*)(r0);
        float4 a1 = *(const float4*)(r0 + 4);
        float4 c0 = *(const float4*)(r1);
        float4 c1 = *(const float4*)(r1 + 4);
        float2* dst = KTb + ld_d2 * 132 + ld_j8;
        *(float4*)&dst[0] = make_float4(a0.x, c0.x, a0.y, c0.y);
        *(float4*)&dst[2] = make_float4(a0.z, c0.z, a0.w, c0.w);
        *(float4*)&dst[4] = make_float4(a1.x, c1.x, a1.y, c1.y);
        *(float4*)&dst[6] = make_float4(a1.z, c1.z, a1.w, c1.w);
    }
    __syncthreads();

    float tv[4]; int tix[4]; float th[4];
#pragma unroll
    for (int q = 0; q < 4; q++) { tv[q] = -INFINITY; tix[q] = 0; th[q] = -INFINITY; }

    const float2* qbase = Q2 + wrp * 4;

    for (int c = 0; c < 32; c++) {
        int j0 = c * 128;
        // prefetch next chunk into regs (LDG in flight during compute)
        float4 a0, a1, c0, c1;
        if (c + 1 < 32) {
            const float* r0 = Kg + (2 * ld_d2) * N_ + (j0 + 128) + ld_j8;
            const float* r1 = Kg + (2 * ld_d2 + 1) * N_ + (j0 + 128) + ld_j8;
            a0 = *(const float4*)(r0);
            a1 = *(const float4*)(r0 + 4);
            c0 = *(const float4*)(r1);
            c1 = *(const float4*)(r1 + 4);
        }

        const float2* kb = KTb + (c & 1) * (32 * 132);

        // ---- packed score GEMM: acc2[q][s] = f32x2 partial sums over (even d, odd d) ----
        u64 acc2[4][4];
#pragma unroll
        for (int q = 0; q < 4; q++)
#pragma unroll
            for (int s = 0; s < 4; s++) acc2[q][s] = 0ull;

#pragma unroll 8
        for (int d2 = 0; d2 < 32; d2++) {
            const u64* qp = (const u64*)(qbase + d2 * 66);
            ulonglong2 q01 = *(const ulonglong2*)qp;        // queries wrp*4, +1 (broadcast)
            ulonglong2 q23 = *(const ulonglong2*)(qp + 2);  // queries +2, +3
            const u64* kp = (const u64*)(kb + d2 * 132) + lane;
            u64 b0 = kp[0], b1 = kp[32], b2 = kp[64], b3 = kp[96];
            fma2(acc2[0][0], q01.x, b0); fma2(acc2[0][1], q01.x, b1);
            fma2(acc2[0][2], q01.x, b2); fma2(acc2[0][3], q01.x, b3);
            fma2(acc2[1][0], q01.y, b0); fma2(acc2[1][1], q01.y, b1);
            fma2(acc2[1][2], q01.y, b2); fma2(acc2[1][3], q01.y, b3);
            fma2(acc2[2][0], q23.x, b0); fma2(acc2[2][1], q23.x, b1);
            fma2(acc2[2][2], q23.x, b2); fma2(acc2[2][3], q23.x, b3);
            fma2(acc2[3][0], q23.y, b0); fma2(acc2[3][1], q23.y, b1);
            fma2(acc2[3][2], q23.y, b2); fma2(acc2[3][3], q23.y, b3);
        }

        // horizontal add: score[q][s], j = j0 + s*32 + lane
        float sc[4][4];
#pragma unroll
        for (int q = 0; q < 4; q++)
#pragma unroll
            for (int s = 0; s < 4; s++) {
                float2 f = upk2(acc2[q][s]);
                sc[q][s] = f.x + f.y;
            }

        if (c == 0) {
            // preload top-list with slot-0 scores (j = lane): kills the -inf tie storm
#pragma unroll
            for (int q = 0; q < 4; q++) {
                tv[q] = sc[q][0]; tix[q] = lane;
                th[q] = iordf(__reduce_min_sync(FULL, ordf(tv[q])));
                sc[q][0] = -INFINITY;
            }
        }

        // ---- streaming top-32 update ----
#pragma unroll
        for (int q = 0; q < 4; q++) {
            float lmax = fmaxf(fmaxf(sc[q][0], sc[q][1]), fmaxf(sc[q][2], sc[q][3]));
            unsigned m = __ballot_sync(FULL, lmax > th[q]);
            while (m) {
                int src = __ffs(m) - 1; m &= m - 1;
                float v0 = __shfl_sync(FULL, sc[q][0], src);
                float v1 = __shfl_sync(FULL, sc[q][1], src);
                float v2 = __shfl_sync(FULL, sc[q][2], src);
                float v3 = __shfl_sync(FULL, sc[q][3], src);
                float vs[4] = {v0, v1, v2, v3};
#pragma unroll
                for (int s = 0; s < 4; s++) {
                    float vn = vs[s];
                    if (vn > th[q]) {          // warp-uniform
                        int jn = j0 + (s << 5) + src;
                        unsigned tied = __ballot_sync(FULL, tv[q] == th[q]);
                        int ml;
                        if (__popc(tied) > 1) {
                            unsigned key = ((tied >> lane) & 1u)
                                         ? (((unsigned)tix[q] << 5) | lane) : 0u;
                            ml = (int)(__reduce_max_sync(FULL, key) & 31u);
                        } else {
                            ml = __ffs(tied) - 1;
                        }
                        if (lane == ml) { tv[q] = vn; tix[q] = jn; }
                        th[q] = iordf(__reduce_min_sync(FULL, ordf(tv[q])));
                    }
                }
            }
        }

        // ---- stage next K chunk; one barrier per chunk ----
        if (c + 1 < 32) {
            float2* dst = KTb + ((c + 1) & 1) * (32 * 132) + ld_d2 * 132 + ld_j8;
            *(float4*)&dst[0] = make_float4(a0.x, c0.x, a0.y, c0.y);
            *(float4*)&dst[2] = make_float4(a0.z, c0.z, a0.w, c0.w);
            *(float4*)&dst[4] = make_float4(a1.x, c1.x, a1.y, c1.y);
            *(float4*)&dst[6] = make_float4(a1.z, c1.z, a1.w, c1.w);
        }
        __syncthreads();
    }

    // ---- finalize: sort, masked softmax, (wt, idx) tables ----
    int kd4[4];
#pragma unroll
    for (int q = 0; q < 4; q++) kd4[q] = g_kdyn[b * N_ + i0 + wrp * 4 + q];

#pragma unroll 1
    for (int q = 0; q < 4; q++) {
        int il = wrp * 4 + q;
        unsigned long long key =
            ((unsigned long long)(~ordf(tv[q])) << 32) | (unsigned)tix[q];
#pragma unroll
        for (int k = 2; k <= 32; k <<= 1) {
#pragma unroll
            for (int j = k >> 1; j > 0; j >>= 1) {
                unsigned long long partner = __shfl_xor_sync(FULL, key, j);
                bool dirAsc = ((lane & k) == 0);
                bool lower  = ((lane & j) == 0);
                unsigned long long mn = key < partner ? key : partner;
                unsigned long long mx = key < partner ? partner : key;
                key = (lower == dirAsc) ? mn : mx;
            }
        }
        float val = iordf(~(unsigned)(key >> 32));
        int   idx = (int)(key & 0xffffffffull);

        int kd = kd4[q];
        float sv = val * 0.125f;                    // 1/sqrt(64)
        float mx = __shfl_sync(FULL, sv, 0);
        float e  = (lane < kd) ? expf(sv - mx) : 0.f;
        float ssum = e;
#pragma unroll
        for (int o = 16; o; o >>= 1) ssum += __shfl_xor_sync(FULL, ssum, o);
        float wt = e / ssum;

        Wsm[il * 33 + lane] = wt;
        Ism[il * 33 + lane] = idx;
    }
    __syncthreads();

    // ---- gather: thread = (i = tid&63, dq = tid>>6 -> 8 d's) ----
    {
        int i  = tid & 63;
        int dq = tid >> 6;
        const float* Wr = &Wsm[i * 33];
        const int*   Ir = &Ism[i * 33];
        float4 o0 = make_float4(0.f, 0.f, 0.f, 0.f);
        float4 o1 = make_float4(0.f, 0.f, 0.f, 0.f);
#pragma unroll 4
        for (int k = 0; k < 32; k++) {
            float wv = Wr[k];
            int   ix = Ir[k];
            const float* vrow = Vg + ix * DH_ + dq * 8;
            float4 a = *(const float4*)(vrow);
            float4 c = *(const float4*)(vrow + 4);
            o0.x += wv * a.x; o0.y += wv * a.y; o0.z += wv * a.z; o0.w += wv * a.w;
            o1.x += wv * c.x; o1.y += wv * c.y; o1.z += wv * c.z; o1.w += wv * c.w;
        }
        float* Ab = g_A + (b * C_ + h * 64) * N_ + i0 + i;
        float ov[8] = {o0.x, o0.y, o0.z, o0.w, o1.x, o1.y, o1.z, o1.w};
#pragma unroll
        for (int s = 0; s < 8; s++) {
            int d = dq * 8 + s;
            Ab[d * N_] = ov[s];
        }
    }
}

// ================= kernel 4: proj GEMM + bias + residual (packed FFMA2) =================
__global__ __launch_bounds__(256) void proj_kernel(const float* __restrict__ x,
                                                   const float* __restrict__ w,
                                                   const float* __restrict__ bias,
                                                   float* __restrict__ out) {
    __shared__ float Ws[16][68];
    __shared__ float As[16][132];
    int n0 = blockIdx.x * 128;
    int o0 = blockIdx.y * 64;
    int b  = blockIdx.z;
    int tid = threadIdx.x;
    int ty = tid >> 4, tx = tid & 15;
    const float* Ab = g_A + b * C_ * N_;

    u64 accp[4][4];
#pragma unroll
    for (int a = 0; a < 4; a++)
#pragma unroll
        for (int c = 0; c < 4; c++) accp[a][c] = 0ull;

    for (int c0 = 0; c0 < C_; c0 += 16) {
        {
            int oo = tid >> 2;
            int cc4 = (tid & 3) << 2;
            float4 wv = *(const float4*)(w + (o0 + oo) * C_ + c0 + cc4);
            Ws[cc4 + 0][oo] = wv.x; Ws[cc4 + 1][oo] = wv.y;
            Ws[cc4 + 2][oo] = wv.z; Ws[cc4 + 3][oo] = wv.w;
        }
#pragma unroll
        for (int r = 0; r < 2; r++) {
            int f = tid + r * 256;
            int cc = f >> 5, n4 = (f & 31) << 2;
            *(float4*)&As[cc][n4] = *(const float4*)(Ab + (c0 + cc) * N_ + n0 + n4);
        }
        __syncthreads();
#pragma unroll
        for (int cc = 0; cc < 16; cc++) {
            float4 wv = *(float4*)&Ws[cc][ty * 4];
            ulonglong2 xa = *(ulonglong2*)&As[cc][tx * 8];
            ulonglong2 xb2 = *(ulonglong2*)&As[cc][tx * 8 + 4];
            u64 wd[4] = {pk2(wv.x, wv.x), pk2(wv.y, wv.y), pk2(wv.z, wv.z), pk2(wv.w, wv.w)};
#pragma unroll
            for (int a = 0; a < 4; a++) {
                fma2(accp[a][0], wd[a], xa.x);
                fma2(accp[a][1], wd[a], xa.y);
                fma2(accp[a][2], wd[a], xb2.x);
                fma2(accp[a][3], wd[a], xb2.y);
            }
        }
        __syncthreads();
    }

    const float* xb = x + b * C_ * N_;
    float* ob = out + b * C_ * N_;
#pragma unroll
    for (int a = 0; a < 4; a++) {
        int o = o0 + ty * 4 + a;
        float bs = bias[o];
        float2 p0 = upk2(accp[a][0]);
        float2 p1 = upk2(accp[a][1]);
        float2 p2 = upk2(accp[a][2]);
        float2 p3 = upk2(accp[a][3]);
        float4 x0 = *(const float4*)(xb + o * N_ + n0 + tx * 8);
        float4 x1 = *(const float4*)(xb + o * N_ + n0 + tx * 8 + 4);
        float4 r0 = make_float4(x0.x + bs + p0.x, x0.y + bs + p0.y,
                                x0.z + bs + p1.x, x0.w + bs + p1.y);
        float4 r1 = make_float4(x1.x + bs + p2.x, x1.y + bs + p2.y,
                                x1.z + bs + p3.x, x1.w + bs + p3.y);
        *(float4*)(ob + o * N_ + n0 + tx * 8)     = r0;
        *(float4*)(ob + o * N_ + n0 + tx * 8 + 4) = r1;
    }
}

// ================= launch =================
extern "C" void kernel_launch(void* const* d_in, const int* in_sizes, int n_in,
                              void* d_out, int out_size) {
    const float* x      = (const float*)d_in[0];
    const float* w_qkv  = (const float*)d_in[1];
    const float* w_proj = (const float*)d_in[2];
    const float* b_proj = (const float*)d_in[3];
    const float* w_g1   = (const float*)d_in[4];
    const float* b_g1   = (const float*)d_in[5];
    const float* w_g2   = (const float*)d_in[6];
    const float* b_g2   = (const float*)d_in[7];
    float* out = (float*)d_out;

    qkv_gemm_kernel<<<dim3(N_ / 128, (3 * C_) / 64, B_), 256>>>(x, w_qkv);
    gate_kernel<<<dim3(N_ / 16, B_), 128>>>(x, w_g1, b_g1, w_g2, b_g2);

    const int attn_smem = (32 * 66 + 2 * 32 * 132) * 8;   // 84480 B
    cudaFuncSetAttribute(attn_kernel, cudaFuncAttributeMaxDynamicSharedMemorySize, attn_smem);
    attn_kernel<<<dim3(N_ / 64, HEADS_, B_), 512, attn_smem>>>();

    proj_kernel<<<dim3(N_ / 128, C_ / 64, B_), 256>>>(x, w_proj, b_proj, out);
}

// round 11
// speedup vs baseline: 4.2342x; 1.2667x over previous
#include <cuda_runtime.h>
#include <math.h>

#define FULL 0xffffffffu
#define B_     2
#define C_     512
#define N_     4096
#define HEADS_ 8
#define DH_    64
#define KMAX_  32

typedef unsigned long long u64;

// ---------------- scratch (device globals; no allocation allowed) ----------------
// Q,K stored d-pair interleaved: as float2 rows [b][h][d2][n], d2 = d/2,
// element = (val[2*d2][n], val[2*d2+1][n])
__device__ float g_Q[B_ * HEADS_ * DH_ * N_];
__device__ float g_K[B_ * HEADS_ * DH_ * N_];
__device__ float g_V[B_ * HEADS_ * N_ * DH_];   // [b][h][n][d]
__device__ float g_A[B_ * C_ * N_];             // attention out, [b][c][n]
__device__ int   g_kdyn[B_ * N_];

// ---------------- helpers ----------------
__device__ __forceinline__ unsigned ordf(float v) {
    unsigned u = __float_as_uint(v);
    return (u & 0x80000000u) ? ~u : (u | 0x80000000u);
}
__device__ __forceinline__ float iordf(unsigned o) {
    unsigned u = (o & 0x80000000u) ? (o & 0x7fffffffu) : ~o;
    return __uint_as_float(u);
}
__device__ __forceinline__ u64 pk2(float lo, float hi) {
    u64 r; asm("mov.b64 %0,{%1,%2};" : "=l"(r) : "f"(lo), "f"(hi)); return r;
}
__device__ __forceinline__ void fma2(u64& d, u64 a, u64 b) {
    asm("fma.rn.f32x2 %0,%1,%2,%0;" : "+l"(d) : "l"(a), "l"(b));
}
__device__ __forceinline__ float2 upk2(u64 v) {
    float2 f; asm("mov.b64 {%0,%1},%2;" : "=f"(f.x), "=f"(f.y) : "l"(v)); return f;
}
__device__ __forceinline__ void cpa16(unsigned dst, const void* src) {
    asm volatile("cp.async.cg.shared.global [%0], [%1], 16;" :: "r"(dst), "l"(src));
}
__device__ __forceinline__ void cpa_commit() { asm volatile("cp.async.commit_group;"); }
__device__ __forceinline__ void cpa_wait0()  { asm volatile("cp.async.wait_group 0;" ::: "memory"); }

// ================= kernel 1: QKV GEMM (packed FFMA2, interleaved Q/K output) ====
__global__ __launch_bounds__(256) void qkv_gemm_kernel(const float* __restrict__ x,
                                                       const float* __restrict__ w) {
    __shared__ float Ws[16][68];
    __shared__ float Xs[16][132];
    __shared__ float St[64][132];
    int n0 = blockIdx.x * 128;
    int o0 = blockIdx.y * 64;
    int b  = blockIdx.z;
    int tid = threadIdx.x;
    int ty = tid >> 4, tx = tid & 15;
    const float* xb = x + b * C_ * N_;

    u64 accp[4][4];
#pragma unroll
    for (int a = 0; a < 4; a++)
#pragma unroll
        for (int c = 0; c < 4; c++) accp[a][c] = 0ull;

    for (int c0 = 0; c0 < C_; c0 += 16) {
        {   // W tile transpose-load
            int oo = tid >> 2;
            int cc4 = (tid & 3) << 2;
            float4 wv = *(const float4*)(w + (o0 + oo) * C_ + c0 + cc4);
            Ws[cc4 + 0][oo] = wv.x; Ws[cc4 + 1][oo] = wv.y;
            Ws[cc4 + 2][oo] = wv.z; Ws[cc4 + 3][oo] = wv.w;
        }
#pragma unroll
        for (int r = 0; r < 2; r++) {
            int f = tid + r * 256;
            int cc = f >> 5, n4 = (f & 31) << 2;
            *(float4*)&Xs[cc][n4] = *(const float4*)(xb + (c0 + cc) * N_ + n0 + n4);
        }
        __syncthreads();
#pragma unroll
        for (int cc = 0; cc < 16; cc++) {
            float4 wv = *(float4*)&Ws[cc][ty * 4];
            ulonglong2 xa = *(ulonglong2*)&Xs[cc][tx * 8];
            ulonglong2 xb2 = *(ulonglong2*)&Xs[cc][tx * 8 + 4];
            u64 wd[4] = {pk2(wv.x, wv.x), pk2(wv.y, wv.y), pk2(wv.z, wv.z), pk2(wv.w, wv.w)};
#pragma unroll
            for (int a = 0; a < 4; a++) {
                fma2(accp[a][0], wd[a], xa.x);
                fma2(accp[a][1], wd[a], xa.y);
                fma2(accp[a][2], wd[a], xb2.x);
                fma2(accp[a][3], wd[a], xb2.y);
            }
        }
        __syncthreads();
    }

    float acc[4][8];
#pragma unroll
    for (int a = 0; a < 4; a++)
#pragma unroll
        for (int c = 0; c < 4; c++) {
            float2 f = upk2(accp[a][c]);
            acc[a][2 * c] = f.x; acc[a][2 * c + 1] = f.y;
        }

    int sel = o0 >> 9;            // 0:Q 1:K 2:V
    int h   = (o0 & 511) >> 6;
    if (sel < 2) {
        // interleaved write: row d2 = d/2, float2 = (d even, d odd)
        float2* dst = (float2*)((sel == 0 ? g_Q : g_K) + (b * HEADS_ + h) * DH_ * N_);
#pragma unroll
        for (int a = 0; a < 4; a += 2) {
            int d2 = ty * 2 + (a >> 1);
            float2* d2p = dst + d2 * N_ + n0 + tx * 8;
#pragma unroll
            for (int c = 0; c < 8; c += 2) {
                *(float4*)&d2p[c] = make_float4(acc[a][c], acc[a + 1][c],
                                                acc[a][c + 1], acc[a + 1][c + 1]);
            }
        }
    } else {
#pragma unroll
        for (int a = 0; a < 4; a++)
#pragma unroll
            for (int c = 0; c < 8; c++) St[ty * 4 + a][tx * 8 + c] = acc[a][c];
        __syncthreads();
        float* dst = g_V + ((b * HEADS_ + h) * N_ + n0) * DH_;
#pragma unroll
        for (int r = 0; r < 8; r++) {
            int f = tid + r * 256;
            int nl = f >> 4, dd = (f & 15) << 2;
            float4 v = make_float4(St[dd][nl], St[dd + 1][nl], St[dd + 2][nl], St[dd + 3][nl]);
            *(float4*)(dst + nl * DH_ + dd) = v;
        }
    }
}

// ================= kernel 2: gate MLP -> k_dyn =================
__global__ __launch_bounds__(128) void gate_kernel(const float* __restrict__ x,
                                                   const float* __restrict__ w1,
                                                   const float* __restrict__ b1,
                                                   const float* __restrict__ w2,
                                                   const float* __restrict__ b2) {
    __shared__ float Xs[512][17];
    __shared__ float T1s[128][17];
    int n0 = blockIdx.x * 16;
    int b  = blockIdx.y;
    int tid = threadIdx.x;
    const float* xb = x + b * C_ * N_;
#pragma unroll 8
    for (int r = 0; r < 64; r++) {
        int f = tid + r * 128;
        int c = f >> 4, nn = f & 15;
        Xs[c][nn] = xb[c * N_ + n0 + nn];
    }
    __syncthreads();
    int nn = tid & 15, ob = tid >> 4;
    for (int rep = 0; rep < 16; rep++) {
        int o = ob + rep * 8;
        float acc = b1[o];
        const float* wr = w1 + o * 512;
        for (int c = 0; c < 512; c += 4) {
            float4 wv = *(const float4*)(wr + c);
            acc += wv.x * Xs[c][nn] + wv.y * Xs[c + 1][nn]
                 + wv.z * Xs[c + 2][nn] + wv.w * Xs[c + 3][nn];
        }
        T1s[o][nn] = fmaxf(acc, 0.f);
    }
    __syncthreads();
    {
        int p = tid >> 3;
        int seg = tid & 7;
        float s = 0.f;
        for (int o = 0; o < 16; o++) s += w2[seg * 16 + o] * T1s[seg * 16 + o][p];
#pragma unroll
        for (int o = 4; o; o >>= 1) s += __shfl_xor_sync(FULL, s, o);
        if (seg == 0) {
            s += b2[0];
            float tau = 1.f / (1.f + expf(-s));
            int kd = (int)(tau * 32.f);
            kd = kd < 4 ? 4 : (kd > 32 ? 32 : kd);
            g_kdyn[b * N_ + n0 + p] = kd;
        }
    }
}

// ================= kernel 3: fused KNN attention =================
// 512 threads, 2 blocks/SM. Warp w owns queries w*4..w*4+3 of a 64-query tile.
// Sorted-list top-32: warp keeps 32 composite keys ((~ordf(v))<<32 | idx) sorted
// ascending across lanes (== value desc, idx asc). Insertion = ballot rank +
// shfl-up shift. K tiles staged via cp.async (pre-interleaved layout).
__global__ __launch_bounds__(512, 2) void attn_kernel() {
    extern __shared__ char smraw[];
    float2* Q2  = (float2*)smraw;                      // [32 d2][66]
    float2* KTb = (float2*)(smraw + 32 * 66 * 8);      // 2 x [32 d2][132]
    float*  Wsm = (float*)smraw;                       // alias after streaming: [64][33]
    int*    Ism = (int*)(smraw + 64 * 33 * 4);         // alias: [64][33]

    int i0 = blockIdx.x * 64;
    int h  = blockIdx.y;
    int b  = blockIdx.z;
    int tid = threadIdx.x;
    int lane = tid & 31;
    int wrp  = tid >> 5;            // 0..15
    int bh = b * HEADS_ + h;
    const float2* Qg2 = (const float2*)(g_Q + bh * DH_ * N_);
    const float2* Kg2 = (const float2*)(g_K + bh * DH_ * N_);
    const float*  Vg  = g_V + bh * N_ * DH_;

    int st_d2  = tid >> 4;          // 0..31  (stager row)
    int st_seg = tid & 15;          // 0..15  (8 float2 per seg)

    // ---- load Q tile (straight copy, layout already interleaved) ----
#pragma unroll
    for (int r = 0; r < 2; r++) {
        int f = tid + r * 512;
        int d2 = f >> 5, c4 = (f & 31) << 1;   // c4: float2 index step 2 (16B)
        *(float4*)&Q2[d2 * 66 + c4] = *(const float4*)(Qg2 + d2 * N_ + i0 + c4);
    }

    // ---- prologue: cp.async K chunk 0 -> buf0 ----
    {
        unsigned dst = (unsigned)__cvta_generic_to_shared(KTb + st_d2 * 132 + st_seg * 8);
        const float2* src = Kg2 + st_d2 * N_ + st_seg * 8;
#pragma unroll
        for (int t = 0; t < 4; t++) cpa16(dst + t * 16, src + t * 2);
        cpa_commit();
    }
    cpa_wait0();
    __syncthreads();

    u64 key[4];                      // sorted ascending across lanes per query
    float thv[4];                    // float value of current list max-key (worst kept)
    const float2* qbase = Q2 + wrp * 4;

    for (int c = 0; c < 32; c++) {
        int j0 = c * 128;
        // issue cp.async for next chunk into the other buffer
        if (c + 1 < 32) {
            float2* dstp = KTb + (((c + 1) & 1) ? (32 * 132) : 0) + st_d2 * 132 + st_seg * 8;
            unsigned dst = (unsigned)__cvta_generic_to_shared(dstp);
            const float2* src = Kg2 + st_d2 * N_ + (j0 + 128) + st_seg * 8;
#pragma unroll
            for (int t = 0; t < 4; t++) cpa16(dst + t * 16, src + t * 2);
            cpa_commit();
        }

        const float2* kb = KTb + ((c & 1) ? (32 * 132) : 0);

        // ---- packed score GEMM ----
        u64 acc2[4][4];
#pragma unroll
        for (int q = 0; q < 4; q++)
#pragma unroll
            for (int s = 0; s < 4; s++) acc2[q][s] = 0ull;

#pragma unroll 8
        for (int d2 = 0; d2 < 32; d2++) {
            const u64* qp = (const u64*)(qbase + d2 * 66);
            ulonglong2 q01 = *(const ulonglong2*)qp;
            ulonglong2 q23 = *(const ulonglong2*)(qp + 2);
            const u64* kp = (const u64*)(kb + d2 * 132) + lane;
            u64 b0 = kp[0], b1 = kp[32], b2 = kp[64], b3 = kp[96];
            fma2(acc2[0][0], q01.x, b0); fma2(acc2[0][1], q01.x, b1);
            fma2(acc2[0][2], q01.x, b2); fma2(acc2[0][3], q01.x, b3);
            fma2(acc2[1][0], q01.y, b0); fma2(acc2[1][1], q01.y, b1);
            fma2(acc2[1][2], q01.y, b2); fma2(acc2[1][3], q01.y, b3);
            fma2(acc2[2][0], q23.x, b0); fma2(acc2[2][1], q23.x, b1);
            fma2(acc2[2][2], q23.x, b2); fma2(acc2[2][3], q23.x, b3);
            fma2(acc2[3][0], q23.y, b0); fma2(acc2[3][1], q23.y, b1);
            fma2(acc2[3][2], q23.y, b2); fma2(acc2[3][3], q23.y, b3);
        }

        float sc[4][4];
#pragma unroll
        for (int q = 0; q < 4; q++)
#pragma unroll
            for (int s = 0; s < 4; s++) {
                float2 f = upk2(acc2[q][s]);
                sc[q][s] = f.x + f.y;       // score for j = j0 + s*32 + lane
            }

        if (c == 0) {
            // init list from slot 0 (j = lane), bitonic sort ascending keys
#pragma unroll
            for (int q = 0; q < 4; q++) {
                u64 k0 = ((u64)(~ordf(sc[q][0])) << 32) | (unsigned)lane;
#pragma unroll
                for (int kk = 2; kk <= 32; kk <<= 1) {
#pragma unroll
                    for (int j = kk >> 1; j > 0; j >>= 1) {
                        u64 partner = __shfl_xor_sync(FULL, k0, j);
                        bool dirAsc = ((lane & kk) == 0);
                        bool lower  = ((lane & j) == 0);
                        u64 mn = k0 < partner ? k0 : partner;
                        u64 mx = k0 < partner ? partner : k0;
                        k0 = (lower == dirAsc) ? mn : mx;
                    }
                }
                key[q] = k0;
                u64 k31 = __shfl_sync(FULL, k0, 31);
                thv[q] = iordf(~(unsigned)(k31 >> 32));
                sc[q][0] = -INFINITY;       // slot 0 consumed
            }
        }

        // ---- streaming insert (sorted-list shift) ----
#pragma unroll
        for (int q = 0; q < 4; q++) {
#pragma unroll
            for (int s = 0; s < 4; s++) {
                unsigned m = __ballot_sync(FULL, sc[q][s] > thv[q]);
                while (m) {
                    int src = __ffs(m) - 1; m &= m - 1;
                    float v = __shfl_sync(FULL, sc[q][s], src);
                    if (v > thv[q]) {       // warp-uniform
                        u64 cnd = ((u64)(~ordf(v)) << 32)
                                | (unsigned)(j0 + (s << 5) + src);
                        unsigned below = __ballot_sync(FULL, key[q] < cnd);
                        int pos = __popc(below);
                        u64 sh = __shfl_up_sync(FULL, key[q], 1);
                        key[q] = (lane < pos) ? key[q] : (lane == pos ? cnd : sh);
                        u64 k31 = __shfl_sync(FULL, key[q], 31);
                        thv[q] = iordf(~(unsigned)(k31 >> 32));
                    }
                }
            }
        }

        cpa_wait0();
        __syncthreads();
    }

    // ---- finalize: list already sorted (value desc, idx asc) ----
    int kd4[4];
#pragma unroll
    for (int q = 0; q < 4; q++) kd4[q] = g_kdyn[b * N_ + i0 + wrp * 4 + q];

#pragma unroll
    for (int q = 0; q < 4; q++) {
        int il = wrp * 4 + q;
        float val = iordf(~(unsigned)(key[q] >> 32));
        int   idx = (int)(key[q] & 0xffffffffull);

        int kd = kd4[q];
        float sv = val * 0.125f;                    // 1/sqrt(64)
        float mx = __shfl_sync(FULL, sv, 0);        // rank-0 = max
        float e  = (lane < kd) ? expf(sv - mx) : 0.f;
        float ssum = e;
#pragma unroll
        for (int o = 16; o; o >>= 1) ssum += __shfl_xor_sync(FULL, ssum, o);
        float wt = e / ssum;

        Wsm[il * 33 + lane] = wt;
        Ism[il * 33 + lane] = idx;
    }
    __syncthreads();

    // ---- gather: thread = (i = tid&63, dq = tid>>6 -> 8 d's) ----
    {
        int i  = tid & 63;
        int dq = tid >> 6;
        const float* Wr = &Wsm[i * 33];
        const int*   Ir = &Ism[i * 33];
        float4 o0 = make_float4(0.f, 0.f, 0.f, 0.f);
        float4 o1 = make_float4(0.f, 0.f, 0.f, 0.f);
#pragma unroll 4
        for (int k = 0; k < 32; k++) {
            float wv = Wr[k];
            int   ix = Ir[k];
            const float* vrow = Vg + ix * DH_ + dq * 8;
            float4 a = *(const float4*)(vrow);
            float4 cc = *(const float4*)(vrow + 4);
            o0.x += wv * a.x;  o0.y += wv * a.y;  o0.z += wv * a.z;  o0.w += wv * a.w;
            o1.x += wv * cc.x; o1.y += wv * cc.y; o1.z += wv * cc.z; o1.w += wv * cc.w;
        }
        float* Ab = g_A + (b * C_ + h * 64) * N_ + i0 + i;
        float ov[8] = {o0.x, o0.y, o0.z, o0.w, o1.x, o1.y, o1.z, o1.w};
#pragma unroll
        for (int s = 0; s < 8; s++) {
            int d = dq * 8 + s;
            Ab[d * N_] = ov[s];
        }
    }
}

// ================= kernel 4: proj GEMM + bias + residual (packed FFMA2) =================
__global__ __launch_bounds__(256) void proj_kernel(const float* __restrict__ x,
                                                   const float* __restrict__ w,
                                                   const float* __restrict__ bias,
                                                   float* __restrict__ out) {
    __shared__ float Ws[16][68];
    __shared__ float As[16][132];
    int n0 = blockIdx.x * 128;
    int o0 = blockIdx.y * 64;
    int b  = blockIdx.z;
    int tid = threadIdx.x;
    int ty = tid >> 4, tx = tid & 15;
    const float* Ab = g_A + b * C_ * N_;

    u64 accp[4][4];
#pragma unroll
    for (int a = 0; a < 4; a++)
#pragma unroll
        for (int c = 0; c < 4; c++) accp[a][c] = 0ull;

    for (int c0 = 0; c0 < C_; c0 += 16) {
        {
            int oo = tid >> 2;
            int cc4 = (tid & 3) << 2;
            float4 wv = *(const float4*)(w + (o0 + oo) * C_ + c0 + cc4);
            Ws[cc4 + 0][oo] = wv.x; Ws[cc4 + 1][oo] = wv.y;
            Ws[cc4 + 2][oo] = wv.z; Ws[cc4 + 3][oo] = wv.w;
        }
#pragma unroll
        for (int r = 0; r < 2; r++) {
            int f = tid + r * 256;
            int cc = f >> 5, n4 = (f & 31) << 2;
            *(float4*)&As[cc][n4] = *(const float4*)(Ab + (c0 + cc) * N_ + n0 + n4);
        }
        __syncthreads();
#pragma unroll
        for (int cc = 0; cc < 16; cc++) {
            float4 wv = *(float4*)&Ws[cc][ty * 4];
            ulonglong2 xa = *(ulonglong2*)&As[cc][tx * 8];
            ulonglong2 xb2 = *(ulonglong2*)&As[cc][tx * 8 + 4];
            u64 wd[4] = {pk2(wv.x, wv.x), pk2(wv.y, wv.y), pk2(wv.z, wv.z), pk2(wv.w, wv.w)};
#pragma unroll
            for (int a = 0; a < 4; a++) {
                fma2(accp[a][0], wd[a], xa.x);
                fma2(accp[a][1], wd[a], xa.y);
                fma2(accp[a][2], wd[a], xb2.x);
                fma2(accp[a][3], wd[a], xb2.y);
            }
        }
        __syncthreads();
    }

    const float* xb = x + b * C_ * N_;
    float* ob = out + b * C_ * N_;
#pragma unroll
    for (int a = 0; a < 4; a++) {
        int o = o0 + ty * 4 + a;
        float bs = bias[o];
        float2 p0 = upk2(accp[a][0]);
        float2 p1 = upk2(accp[a][1]);
        float2 p2 = upk2(accp[a][2]);
        float2 p3 = upk2(accp[a][3]);
        float4 x0 = *(const float4*)(xb + o * N_ + n0 + tx * 8);
        float4 x1 = *(const float4*)(xb + o * N_ + n0 + tx * 8 + 4);
        float4 r0 = make_float4(x0.x + bs + p0.x, x0.y + bs + p0.y,
                                x0.z + bs + p1.x, x0.w + bs + p1.y);
        float4 r1 = make_float4(x1.x + bs + p2.x, x1.y + bs + p2.y,
                                x1.z + bs + p3.x, x1.w + bs + p3.y);
        *(float4*)(ob + o * N_ + n0 + tx * 8)     = r0;
        *(float4*)(ob + o * N_ + n0 + tx * 8 + 4) = r1;
    }
}

// ================= launch =================
extern "C" void kernel_launch(void* const* d_in, const int* in_sizes, int n_in,
                              void* d_out, int out_size) {
    const float* x      = (const float*)d_in[0];
    const float* w_qkv  = (const float*)d_in[1];
    const float* w_proj = (const float*)d_in[2];
    const float* b_proj = (const float*)d_in[3];
    const float* w_g1   = (const float*)d_in[4];
    const float* b_g1   = (const float*)d_in[5];
    const float* w_g2   = (const float*)d_in[6];
    const float* b_g2   = (const float*)d_in[7];
    float* out = (float*)d_out;

    qkv_gemm_kernel<<<dim3(N_ / 128, (3 * C_) / 64, B_), 256>>>(x, w_qkv);
    gate_kernel<<<dim3(N_ / 16, B_), 128>>>(x, w_g1, b_g1, w_g2, b_g2);

    const int attn_smem = (32 * 66 + 2 * 32 * 132) * 8;   // 84480 B
    cudaFuncSetAttribute(attn_kernel, cudaFuncAttributeMaxDynamicSharedMemorySize, attn_smem);
    attn_kernel<<<dim3(N_ / 64, HEADS_, B_), 512, attn_smem>>>();

    proj_kernel<<<dim3(N_ / 128, C_ / 64, B_), 256>>>(x, w_proj, b_proj, out);
}